// round 1
// baseline (speedup 1.0000x reference)
#include <cuda_runtime.h>
#include <cuda_bf16.h>
#include <math.h>

#define BATCH 512
#define HEADS 4
#define SDIM  256
#define PPIX  196
#define DH    64

// ---------------- scratch (device globals; no allocation allowed) ----------
#define QKV_ELEMS (BATCH * HEADS * PPIX * DH)   // 25,690,112
__device__ float g_q[QKV_ELEMS];
__device__ float g_k[QKV_ELEMS];
__device__ float g_v[QKV_ELEMS];
__device__ float g_av[BATCH * PPIX * SDIM];     // flat (h*P*D + p*D + d) per batch

// ============================================================================
// Kernel 1: fused QKV projection.
// For each batch b: t_w[o,p] = sum_c w[o,c] * x[b,c,p] + bias[o]  (w in {q,k,v})
// split_heads: q[b,h,p,d] = t[b, h*64+d, p]
// Tiles: BM=64 (out ch), BN=64 (pixels), BK=16. 16x16 threads, 4x4 micro-tile.
// ============================================================================
__global__ void qkv_kernel(const float* __restrict__ x,
                           const float* __restrict__ wq, const float* __restrict__ bq,
                           const float* __restrict__ wk, const float* __restrict__ bk,
                           const float* __restrict__ wv, const float* __restrict__ bv)
{
    const int b  = blockIdx.z;
    const int m0 = blockIdx.y * 64;
    const int n0 = blockIdx.x * 64;
    const int tx = threadIdx.x, ty = threadIdx.y;
    const int tid = ty * 16 + tx;

    __shared__ float sW[3][64][16];
    __shared__ float sX[16][64];

    const float* ws[3] = {wq, wk, wv};

    float acc[3][4][4];
    #pragma unroll
    for (int w = 0; w < 3; w++)
        #pragma unroll
        for (int i = 0; i < 4; i++)
            #pragma unroll
            for (int j = 0; j < 4; j++) acc[w][i][j] = 0.f;

    for (int k0 = 0; k0 < SDIM; k0 += 16) {
        #pragma unroll
        for (int w = 0; w < 3; w++) {
            for (int idx = tid; idx < 64 * 16; idx += 256) {
                int o = idx >> 4, c = idx & 15;
                sW[w][o][c] = ws[w][(m0 + o) * SDIM + k0 + c];
            }
        }
        for (int idx = tid; idx < 16 * 64; idx += 256) {
            int c = idx >> 6, p = idx & 63;
            int gp = n0 + p;
            sX[c][p] = (gp < PPIX) ? x[((size_t)b * SDIM + k0 + c) * PPIX + gp] : 0.f;
        }
        __syncthreads();

        #pragma unroll
        for (int kk = 0; kk < 16; kk++) {
            float xv[4], a[3][4];
            #pragma unroll
            for (int j = 0; j < 4; j++) xv[j] = sX[kk][tx * 4 + j];
            #pragma unroll
            for (int w = 0; w < 3; w++)
                #pragma unroll
                for (int i = 0; i < 4; i++) a[w][i] = sW[w][ty * 4 + i][kk];
            #pragma unroll
            for (int w = 0; w < 3; w++)
                #pragma unroll
                for (int i = 0; i < 4; i++)
                    #pragma unroll
                    for (int j = 0; j < 4; j++)
                        acc[w][i][j] += a[w][i] * xv[j];
        }
        __syncthreads();
    }

    const float* bs[3] = {bq, bk, bv};
    float* outs[3] = {g_q, g_k, g_v};
    #pragma unroll
    for (int w = 0; w < 3; w++) {
        #pragma unroll
        for (int i = 0; i < 4; i++) {
            int o = m0 + ty * 4 + i;
            int h = o >> 6, d = o & 63;
            float bias = bs[w][o];
            #pragma unroll
            for (int j = 0; j < 4; j++) {
                int p = n0 + tx * 4 + j;
                if (p < PPIX)
                    outs[w][(((size_t)b * HEADS + h) * PPIX + p) * DH + d] = acc[w][i][j] + bias;
            }
        }
    }
}

// ============================================================================
// Kernel 2: attention per (b, h, qtile of 64).
//   S = Q K^T / 8  (64 x 196, padded to 256 cols)
//   softmax rows (sum folded into AV epilogue)
//   AV = S V      (64 x 64)
// Dynamic smem: sQ[64][65] + sKV[64][65] + sS[64][260] + sSum[64]
// ============================================================================
__global__ void attn_kernel()
{
    const int b  = blockIdx.z;
    const int h  = blockIdx.y;
    const int q0 = blockIdx.x * 64;
    const int tx = threadIdx.x, ty = threadIdx.y;
    const int tid = ty * 16 + tx;

    extern __shared__ float sm[];
    float* sQ   = sm;                  // 64*65
    float* sKV  = sQ + 64 * 65;        // 64*65
    float* sS   = sKV + 64 * 65;       // 64*260
    float* sSum = sS + 64 * 260;       // 64

    const size_t bh = (size_t)b * HEADS + h;
    const float* Qg = g_q + bh * PPIX * DH;
    const float* Kg = g_k + bh * PPIX * DH;
    const float* Vg = g_v + bh * PPIX * DH;

    // load Q tile (zero-pad invalid queries)
    for (int idx = tid; idx < 64 * 64; idx += 256) {
        int q = idx >> 6, d = idx & 63;
        int gq = q0 + q;
        sQ[q * 65 + d] = (gq < PPIX) ? Qg[gq * DH + d] : 0.f;
    }

    // ---------------- phase A: scores ----------------
    for (int kt = 0; kt < 4; kt++) {
        int k0 = kt * 64;
        __syncthreads();   // Q ready (kt=0) / prior compute done reading sKV
        for (int idx = tid; idx < 64 * 64; idx += 256) {
            int k = idx >> 6, d = idx & 63;
            int gk = k0 + k;
            sKV[k * 65 + d] = (gk < PPIX) ? Kg[gk * DH + d] : 0.f;
        }
        __syncthreads();

        float acc[4][4] = {};
        #pragma unroll 16
        for (int d = 0; d < 64; d++) {
            float qv[4], kv[4];
            #pragma unroll
            for (int i = 0; i < 4; i++) qv[i] = sQ[(ty * 4 + i) * 65 + d];
            #pragma unroll
            for (int j = 0; j < 4; j++) kv[j] = sKV[(tx * 4 + j) * 65 + d];
            #pragma unroll
            for (int i = 0; i < 4; i++)
                #pragma unroll
                for (int j = 0; j < 4; j++) acc[i][j] += qv[i] * kv[j];
        }
        #pragma unroll
        for (int i = 0; i < 4; i++)
            #pragma unroll
            for (int j = 0; j < 4; j++)
                sS[(ty * 4 + i) * 260 + k0 + tx * 4 + j] = acc[i][j] * 0.125f;
    }
    __syncthreads();

    // ---------------- phase B: softmax (4 threads per row) ----------------
    {
        int row = tid >> 2, j = tid & 3;
        float* srow = sS + row * 260;
        float m = -1e30f;
        for (int c = j; c < PPIX; c += 4) m = fmaxf(m, srow[c]);
        m = fmaxf(m, __shfl_xor_sync(0xffffffffu, m, 1));
        m = fmaxf(m, __shfl_xor_sync(0xffffffffu, m, 2));
        float s = 0.f;
        for (int c = j; c < 256; c += 4) {
            float e = (c < PPIX) ? expf(srow[c] - m) : 0.f;
            srow[c] = e;
            s += e;
        }
        s += __shfl_xor_sync(0xffffffffu, s, 1);
        s += __shfl_xor_sync(0xffffffffu, s, 2);
        if (j == 0) sSum[row] = s;
    }
    __syncthreads();

    // ---------------- phase C: AV ----------------
    float acc[4][4] = {};
    for (int kt = 0; kt < 4; kt++) {
        int k0 = kt * 64;
        for (int idx = tid; idx < 64 * 64; idx += 256) {
            int k = idx >> 6, d = idx & 63;
            int gk = k0 + k;
            sKV[k * 65 + d] = (gk < PPIX) ? Vg[gk * DH + d] : 0.f;
        }
        __syncthreads();
        #pragma unroll 16
        for (int kk = 0; kk < 64; kk++) {
            float sv[4], vv[4];
            #pragma unroll
            for (int i = 0; i < 4; i++) sv[i] = sS[(ty * 4 + i) * 260 + k0 + kk];
            #pragma unroll
            for (int j = 0; j < 4; j++) vv[j] = sKV[kk * 65 + tx * 4 + j];
            #pragma unroll
            for (int i = 0; i < 4; i++)
                #pragma unroll
                for (int j = 0; j < 4; j++) acc[i][j] += sv[i] * vv[j];
        }
        __syncthreads();
    }

    // epilogue: normalize + write flat av (reference's no-head-transpose layout)
    float* avb = g_av + (size_t)b * (PPIX * SDIM);
    #pragma unroll
    for (int i = 0; i < 4; i++) {
        int q = q0 + ty * 4 + i;
        if (q < PPIX) {
            float inv = 1.f / sSum[ty * 4 + i];
            #pragma unroll
            for (int j = 0; j < 4; j++) {
                int d = tx * 4 + j;
                avb[h * (PPIX * DH) + q * DH + d] = acc[i][j] * inv;
            }
        }
    }
}

// ============================================================================
// Kernel 3: output projection.
// out[b,o,p] = bo[o] + sum_c wo[o,c] * g_av[b, p*256 + c]
// ============================================================================
__global__ void outproj_kernel(const float* __restrict__ wo,
                               const float* __restrict__ bo,
                               float* __restrict__ out)
{
    const int b  = blockIdx.z;
    const int m0 = blockIdx.y * 64;
    const int n0 = blockIdx.x * 64;
    const int tx = threadIdx.x, ty = threadIdx.y;
    const int tid = ty * 16 + tx;

    __shared__ float sW[64][16];
    __shared__ float sM[16][65];

    const float* avb = g_av + (size_t)b * (PPIX * SDIM);
    float acc[4][4] = {};

    for (int k0 = 0; k0 < SDIM; k0 += 16) {
        for (int idx = tid; idx < 64 * 16; idx += 256) {
            int o = idx >> 4, c = idx & 15;
            sW[o][c] = wo[(m0 + o) * SDIM + k0 + c];
        }
        for (int idx = tid; idx < 16 * 64; idx += 256) {
            int p = idx >> 4, c = idx & 15;
            int gp = n0 + p;
            sM[c][p] = (gp < PPIX) ? avb[gp * SDIM + k0 + c] : 0.f;
        }
        __syncthreads();

        #pragma unroll
        for (int kk = 0; kk < 16; kk++) {
            float a[4], xv[4];
            #pragma unroll
            for (int i = 0; i < 4; i++) a[i] = sW[ty * 4 + i][kk];
            #pragma unroll
            for (int j = 0; j < 4; j++) xv[j] = sM[kk][tx * 4 + j];
            #pragma unroll
            for (int i = 0; i < 4; i++)
                #pragma unroll
                for (int j = 0; j < 4; j++) acc[i][j] += a[i] * xv[j];
        }
        __syncthreads();
    }

    #pragma unroll
    for (int i = 0; i < 4; i++) {
        int o = m0 + ty * 4 + i;
        float bias = bo[o];
        #pragma unroll
        for (int j = 0; j < 4; j++) {
            int p = n0 + tx * 4 + j;
            if (p < PPIX)
                out[((size_t)b * SDIM + o) * PPIX + p] = acc[i][j] + bias;
        }
    }
}

// ============================================================================
extern "C" void kernel_launch(void* const* d_in, const int* in_sizes, int n_in,
                              void* d_out, int out_size)
{
    const float* x  = (const float*)d_in[0];
    const float* wq = (const float*)d_in[1];
    const float* bq = (const float*)d_in[2];
    const float* wk = (const float*)d_in[3];
    const float* bk = (const float*)d_in[4];
    const float* wv = (const float*)d_in[5];
    const float* bv = (const float*)d_in[6];
    const float* wo = (const float*)d_in[7];
    const float* bo = (const float*)d_in[8];
    float* out = (float*)d_out;

    dim3 blk(16, 16);

    // Stage 1: fused QKV projection
    qkv_kernel<<<dim3(4, 4, BATCH), blk>>>(x, wq, bq, wk, bk, wv, bv);

    // Stage 2: attention (needs >48KB smem)
    const size_t attn_smem = (64 * 65 + 64 * 65 + 64 * 260 + 64) * sizeof(float); // ~97.75 KB
    cudaFuncSetAttribute(attn_kernel, cudaFuncAttributeMaxDynamicSharedMemorySize,
                         (int)attn_smem);
    attn_kernel<<<dim3(4, HEADS, BATCH), blk, attn_smem>>>();

    // Stage 3: output projection
    outproj_kernel<<<dim3(4, 4, BATCH), blk>>>(wo, bo, out);
}

// round 3
// speedup vs baseline: 1.6019x; 1.6019x over previous
#include <cuda_runtime.h>
#include <cstdint>
#include <math.h>
#include <mma.h>

using namespace nvcuda;

#define BATCH 512
#define HEADS 4
#define SDIM  256
#define PPIX  196
#define DH    64
#define PD    (PPIX * DH)   // 12544

// ---------------- scratch (device globals; no allocation allowed) ----------
#define QKV_ELEMS (BATCH * HEADS * PPIX * DH)
__device__ float g_q[QKV_ELEMS];
__device__ float g_k[QKV_ELEMS];
__device__ float g_v[QKV_ELEMS];
__device__ float g_av[BATCH * PPIX * SDIM];   // per batch: [p][c], c = h*64+d

// round fp32 -> tf32 (rna) once at smem fill; fragments then need no convert
__device__ __forceinline__ float f2tf(float v) {
    uint32_t u;
    asm("cvt.rna.tf32.f32 %0, %1;" : "=r"(u) : "f"(v));
    return __uint_as_float(u);
}

typedef wmma::fragment<wmma::matrix_a, 16, 16, 8, wmma::precision::tf32, wmma::row_major> FragA;
typedef wmma::fragment<wmma::matrix_b, 16, 16, 8, wmma::precision::tf32, wmma::row_major> FragBR;
typedef wmma::fragment<wmma::matrix_b, 16, 16, 8, wmma::precision::tf32, wmma::col_major> FragBC;
typedef wmma::fragment<wmma::accumulator, 16, 16, 8, float> FragC;

// ============================================================================
// Kernel 1: QKV projection.  Per (b, ws): D[o,p] = W[o,:]·x[b,:,p] + bias[o]
// CTA tile 64(M=o) x 64(N=p), K=256 in chunks of 32. 8 warps = 4(M) x 2(N).
// grid = (16 = ntile + 4*mtile, 3, BATCH)
// ============================================================================
__global__ void __launch_bounds__(256)
qkv_tc(const float* __restrict__ x,
       const float* __restrict__ wq, const float* __restrict__ bq,
       const float* __restrict__ wk, const float* __restrict__ bk,
       const float* __restrict__ wv, const float* __restrict__ bv)
{
    __shared__ float sA[64 * 40];   // W chunk  [m][k]   ldm 40
    __shared__ float sB[32 * 72];   // x chunk  [k][p]   ldm 72 (row-major B)
    __shared__ float sC[64 * 68];   // result   [m][n]   ldm 68

    const int tid  = threadIdx.x;
    const int w    = tid >> 5;
    const int lane = tid & 31;
    const int row8 = tid >> 5;
    const int n0 = (blockIdx.x & 3) * 64;
    const int m0 = (blockIdx.x >> 2) * 64;
    const int ws = blockIdx.y;
    const int b  = blockIdx.z;

    const float* W    = (ws == 0) ? wq : (ws == 1) ? wk : wv;
    const float* bias = (ws == 0) ? bq : (ws == 1) ? bk : bv;
    float* Og         = (ws == 0) ? g_q : (ws == 1) ? g_k : g_v;

    const int wm = (w >> 1) * 16;
    const int wn = (w & 1) * 32;

    FragC acc[2];
    wmma::fill_fragment(acc[0], 0.f);
    wmma::fill_fragment(acc[1], 0.f);

    const float* xb = x + (size_t)b * SDIM * PPIX;

    for (int k0 = 0; k0 < SDIM; k0 += 32) {
        #pragma unroll
        for (int r = 0; r < 8; r++) {
            int m = r * 8 + row8;
            sA[m * 40 + lane] = f2tf(W[(size_t)(m0 + m) * SDIM + k0 + lane]);
        }
        #pragma unroll
        for (int r = 0; r < 4; r++) {
            int c = r * 8 + row8;
            const float* xr = xb + (size_t)(k0 + c) * PPIX;
            #pragma unroll
            for (int j = 0; j < 64; j += 32) {
                int p = n0 + j + lane;
                sB[c * 72 + j + lane] = (p < PPIX) ? f2tf(xr[p]) : 0.f;
            }
        }
        __syncthreads();

        #pragma unroll
        for (int kk = 0; kk < 32; kk += 8) {
            FragA a;
            wmma::load_matrix_sync(a, sA + wm * 40 + kk, 40);
            #pragma unroll
            for (int j = 0; j < 2; j++) {
                FragBR bfr;
                wmma::load_matrix_sync(bfr, sB + kk * 72 + wn + j * 16, 72);
                wmma::mma_sync(acc[j], a, bfr, acc[j]);
            }
        }
        __syncthreads();
    }

    wmma::store_matrix_sync(sC + wm * 68 + wn,      acc[0], 68, wmma::mem_row_major);
    wmma::store_matrix_sync(sC + wm * 68 + wn + 16, acc[1], 68, wmma::mem_row_major);
    __syncthreads();

    // write: o = m0 + m, h = m0>>6 (constant), d = m. coalesced over d.
    const int m = tid & 63;
    const int h = m0 >> 6;
    const float bb = bias[m0 + m];
    float* ob = Og + (((size_t)b * HEADS + h) * PPIX) * DH + m;
    #pragma unroll
    for (int i = 0; i < 16; i++) {
        int pl = (tid >> 6) + i * 4;
        int p = n0 + pl;
        if (p < PPIX) ob[(size_t)p * DH] = sC[m * 68 + pl] + bb;
    }
}

// ============================================================================
// Kernel 2: attention per (b, h, qtile of 64), all-wmma.
//   S = (Q*0.125) K^T  (64 x 256 padded)
//   softmax rows
//   AV = P V           (64 x 64)
// ============================================================================
__global__ void __launch_bounds__(256)
attn_tc()
{
    extern __shared__ float sm[];
    float* sQ   = sm;                    // 64*72   (reused as sAV)
    float* sKV  = sQ + 64 * 72;          // 256*72  (K, then V)
    float* sS   = sKV + 256 * 72;        // 64*260
    float* sSum = sS + 64 * 260;         // 64

    const int tid = threadIdx.x;
    const int w   = tid >> 5;
    const int b  = blockIdx.z;
    const int h  = blockIdx.y;
    const int q0 = blockIdx.x * 64;

    const size_t bh = (size_t)b * HEADS + h;
    const float* Qg = g_q + bh * PD;
    const float* Kg = g_k + bh * PD;
    const float* Vg = g_v + bh * PD;

    // ---- fill Q (scaled) ----
    for (int idx = tid; idx < 64 * 64; idx += 256) {
        int q = idx >> 6, d = idx & 63;
        int gq = q0 + q;
        sQ[q * 72 + d] = (gq < PPIX) ? f2tf(Qg[(size_t)gq * DH + d] * 0.125f) : 0.f;
    }
    // ---- fill K (256 rows, zero pad) ----
    for (int idx = tid; idx < 256 * 16; idx += 256) {
        int r = idx >> 4, c4 = (idx & 15) * 4;
        float4 v = make_float4(0.f, 0.f, 0.f, 0.f);
        if (r < PPIX) v = *(const float4*)(Kg + (size_t)r * DH + c4);
        float* dst = sKV + r * 72 + c4;
        dst[0] = f2tf(v.x); dst[1] = f2tf(v.y); dst[2] = f2tf(v.z); dst[3] = f2tf(v.w);
    }
    __syncthreads();

    // ---- phase A: S = Q K^T ----
    {
        const int wm  = (w >> 1) * 16;
        const int wn0 = (w & 1) * 128;
        FragC acc[8];
        #pragma unroll
        for (int j = 0; j < 8; j++) wmma::fill_fragment(acc[j], 0.f);
        #pragma unroll
        for (int kk = 0; kk < 64; kk += 8) {
            FragA a;
            wmma::load_matrix_sync(a, sQ + wm * 72 + kk, 72);
            #pragma unroll
            for (int j = 0; j < 8; j++) {
                FragBC bfr;   // B[k=d][n=kpos] = K[kpos][d] -> col-major
                wmma::load_matrix_sync(bfr, sKV + (wn0 + j * 16) * 72 + kk, 72);
                wmma::mma_sync(acc[j], a, bfr, acc[j]);
            }
        }
        #pragma unroll
        for (int j = 0; j < 8; j++)
            wmma::store_matrix_sync(sS + wm * 260 + wn0 + j * 16, acc[j], 260,
                                    wmma::mem_row_major);
    }
    __syncthreads();

    // ---- softmax (4 threads per row) ----
    {
        int row = tid >> 2, j = tid & 3;
        float* srow = sS + row * 260;
        float m = -1e30f;
        for (int c = j; c < PPIX; c += 4) m = fmaxf(m, srow[c]);
        m = fmaxf(m, __shfl_xor_sync(0xffffffffu, m, 1));
        m = fmaxf(m, __shfl_xor_sync(0xffffffffu, m, 2));
        float s = 0.f;
        for (int c = j; c < 256; c += 4) {
            float e = (c < PPIX) ? f2tf(expf(srow[c] - m)) : 0.f;
            srow[c] = e;
            s += e;
        }
        s += __shfl_xor_sync(0xffffffffu, s, 1);
        s += __shfl_xor_sync(0xffffffffu, s, 2);
        if (j == 0) sSum[row] = s;
    }
    __syncthreads();

    // ---- fill V (overwrites K) ----
    for (int idx = tid; idx < 256 * 16; idx += 256) {
        int r = idx >> 4, c4 = (idx & 15) * 4;
        float4 v = make_float4(0.f, 0.f, 0.f, 0.f);
        if (r < PPIX) v = *(const float4*)(Vg + (size_t)r * DH + c4);
        float* dst = sKV + r * 72 + c4;
        dst[0] = f2tf(v.x); dst[1] = f2tf(v.y); dst[2] = f2tf(v.z); dst[3] = f2tf(v.w);
    }
    __syncthreads();

    // ---- phase C: AV = P V ----
    {
        const int wm = (w >> 1) * 16;
        const int wn = (w & 1) * 32;
        FragC acc[2];
        wmma::fill_fragment(acc[0], 0.f);
        wmma::fill_fragment(acc[1], 0.f);
        #pragma unroll
        for (int k = 0; k < 256; k += 8) {
            FragA a;
            wmma::load_matrix_sync(a, sS + wm * 260 + k, 260);
            #pragma unroll
            for (int j = 0; j < 2; j++) {
                FragBR bfr;   // B[k=kpos][n=d] = V row-major
                wmma::load_matrix_sync(bfr, sKV + k * 72 + wn + j * 16, 72);
                wmma::mma_sync(acc[j], a, bfr, acc[j]);
            }
        }
        __syncthreads();   // done reading sQ as Q
        wmma::store_matrix_sync(sQ + wm * 72 + wn,      acc[0], 72, wmma::mem_row_major);
        wmma::store_matrix_sync(sQ + wm * 72 + wn + 16, acc[1], 72, wmma::mem_row_major);
    }
    __syncthreads();

    // ---- epilogue: normalize, write flat av layout [p][h*64+d] ----
    float* avb = g_av + (size_t)b * (PPIX * SDIM);
    const int d = tid & 63;
    #pragma unroll
    for (int i = 0; i < 16; i++) {
        int q = (tid >> 6) + i * 4;
        int gq = q0 + q;
        if (gq < PPIX) {
            float inv = 1.f / sSum[q];
            avb[(size_t)h * PD + (size_t)gq * DH + d] = sQ[q * 72 + d] * inv;
        }
    }
}

// ============================================================================
// Kernel 3: output projection.  out[b,o,p] = bo[o] + sum_c wo[o,c]*av[b][p][c]
// CTA 64(M=o) x 64(N=p), K=256 chunks of 32. grid = (16, BATCH)
// ============================================================================
__global__ void __launch_bounds__(256)
outproj_tc(const float* __restrict__ wo, const float* __restrict__ bo,
           float* __restrict__ out)
{
    __shared__ float sA[64 * 40];   // wo chunk [m][k]  ldm 40
    __shared__ float sBo[64 * 40];  // av chunk [p][k]  ldm 40 (col-major B)
    __shared__ float sC[64 * 68];

    const int tid  = threadIdx.x;
    const int w    = tid >> 5;
    const int lane = tid & 31;
    const int row8 = tid >> 5;
    const int n0 = (blockIdx.x & 3) * 64;
    const int m0 = (blockIdx.x >> 2) * 64;
    const int b  = blockIdx.y;

    const int wm = (w >> 1) * 16;
    const int wn = (w & 1) * 32;

    FragC acc[2];
    wmma::fill_fragment(acc[0], 0.f);
    wmma::fill_fragment(acc[1], 0.f);

    const float* avb = g_av + (size_t)b * (PPIX * SDIM);

    for (int k0 = 0; k0 < SDIM; k0 += 32) {
        #pragma unroll
        for (int r = 0; r < 8; r++) {
            int m = r * 8 + row8;
            sA[m * 40 + lane] = f2tf(wo[(size_t)(m0 + m) * SDIM + k0 + lane]);
        }
        #pragma unroll
        for (int r = 0; r < 8; r++) {
            int pl = r * 8 + row8;
            int p = n0 + pl;
            sBo[pl * 40 + lane] = (p < PPIX) ? f2tf(avb[(size_t)p * SDIM + k0 + lane]) : 0.f;
        }
        __syncthreads();

        #pragma unroll
        for (int kk = 0; kk < 32; kk += 8) {
            FragA a;
            wmma::load_matrix_sync(a, sA + wm * 40 + kk, 40);
            #pragma unroll
            for (int j = 0; j < 2; j++) {
                FragBC bfr;   // B[k=c][n=p] = av[p][c] -> col-major ldm 40
                wmma::load_matrix_sync(bfr, sBo + (wn + j * 16) * 40 + kk, 40);
                wmma::mma_sync(acc[j], a, bfr, acc[j]);
            }
        }
        __syncthreads();
    }

    wmma::store_matrix_sync(sC + wm * 68 + wn,      acc[0], 68, wmma::mem_row_major);
    wmma::store_matrix_sync(sC + wm * 68 + wn + 16, acc[1], 68, wmma::mem_row_major);
    __syncthreads();

    const int n = tid & 63;
    #pragma unroll
    for (int i = 0; i < 16; i++) {
        int m = (tid >> 6) + i * 4;
        int p = n0 + n;
        if (p < PPIX)
            out[((size_t)b * SDIM + m0 + m) * PPIX + p] = sC[m * 68 + n] + bo[m0 + m];
    }
}

// ============================================================================
extern "C" void kernel_launch(void* const* d_in, const int* in_sizes, int n_in,
                              void* d_out, int out_size)
{
    const float* x  = (const float*)d_in[0];
    const float* wq = (const float*)d_in[1];
    const float* bq = (const float*)d_in[2];
    const float* wk = (const float*)d_in[3];
    const float* bk = (const float*)d_in[4];
    const float* wv = (const float*)d_in[5];
    const float* bv = (const float*)d_in[6];
    const float* wo = (const float*)d_in[7];
    const float* bo = (const float*)d_in[8];
    float* out = (float*)d_out;

    qkv_tc<<<dim3(16, 3, BATCH), 256>>>(x, wq, bq, wk, bk, wv, bv);

    const size_t attn_smem = (64 * 72 + 256 * 72 + 64 * 260 + 64) * sizeof(float); // 158,976
    cudaFuncSetAttribute(attn_tc, cudaFuncAttributeMaxDynamicSharedMemorySize,
                         (int)attn_smem);
    attn_tc<<<dim3(4, HEADS, BATCH), 256, attn_smem>>>();

    outproj_tc<<<dim3(16, BATCH), 256>>>(wo, bo, out);
}

// round 4
// speedup vs baseline: 1.8804x; 1.1739x over previous
#include <cuda_runtime.h>
#include <cstdint>
#include <math.h>
#include <mma.h>

using namespace nvcuda;

#define BATCH 512
#define HEADS 4
#define SDIM  256
#define PPIX  196
#define DH    64
#define PD    (PPIX * DH)
#define NPAD  208              // 13 x 16 key/prob padding

// ---------------- scratch ----------------
#define QKV_ELEMS (BATCH * HEADS * PPIX * DH)
__device__ float g_q[QKV_ELEMS];
__device__ float g_k[QKV_ELEMS];
__device__ float g_v[QKV_ELEMS];
__device__ float g_av[BATCH * PPIX * SDIM];

__device__ __forceinline__ float f2tf(float v) {
    uint32_t u;
    asm("cvt.rna.tf32.f32 %0, %1;" : "=r"(u) : "f"(v));
    return __uint_as_float(u);
}

typedef wmma::fragment<wmma::matrix_a, 16, 16, 8, wmma::precision::tf32, wmma::row_major> FragA;
typedef wmma::fragment<wmma::matrix_b, 16, 16, 8, wmma::precision::tf32, wmma::row_major> FragBR;
typedef wmma::fragment<wmma::matrix_b, 16, 16, 8, wmma::precision::tf32, wmma::col_major> FragBC;
typedef wmma::fragment<wmma::accumulator, 16, 16, 8, float> FragC;

// ============================================================================
// Kernel 1: QKV projection. CTA 128(M=o) x 64(N=p), warp tile 32x32.
// grid = (8 = 4 ntile + 2*mtile*4, 3, BATCH); dyn smem reused for epilogue.
// ============================================================================
__global__ void __launch_bounds__(256)
qkv_tc(const float* __restrict__ x,
       const float* __restrict__ wq, const float* __restrict__ bq,
       const float* __restrict__ wk, const float* __restrict__ bk,
       const float* __restrict__ wv, const float* __restrict__ bv)
{
    extern __shared__ float sm[];
    float* sA = sm;              // 128*40
    float* sB = sm + 128 * 40;   // 32*72
    float* sC = sm;              // reuse: 128*68

    const int tid  = threadIdx.x;
    const int w    = tid >> 5;
    const int lane = tid & 31;
    const int n0 = (blockIdx.x & 3) * 64;
    const int m0 = (blockIdx.x >> 2) * 128;
    const int ws = blockIdx.y;
    const int b  = blockIdx.z;

    const float* W    = (ws == 0) ? wq : (ws == 1) ? wk : wv;
    const float* bias = (ws == 0) ? bq : (ws == 1) ? bk : bv;
    float* Og         = (ws == 0) ? g_q : (ws == 1) ? g_k : g_v;

    const int wm = (w >> 1) * 32;
    const int wn = (w & 1) * 32;

    FragC acc[2][2];
    #pragma unroll
    for (int i = 0; i < 2; i++)
        #pragma unroll
        for (int j = 0; j < 2; j++) wmma::fill_fragment(acc[i][j], 0.f);

    const float* xb = x + (size_t)b * SDIM * PPIX;
    const int bcol = tid & 63, brow = tid >> 6;

    for (int k0 = 0; k0 < SDIM; k0 += 32) {
        #pragma unroll
        for (int r = 0; r < 16; r++) {
            int row = (tid >> 5) + r * 8;
            sA[row * 40 + lane] = f2tf(W[(size_t)(m0 + row) * SDIM + k0 + lane]);
        }
        #pragma unroll
        for (int r = 0; r < 8; r++) {
            int c = brow + r * 4;
            int p = n0 + bcol;
            sB[c * 72 + bcol] = (p < PPIX) ? f2tf(xb[(size_t)(k0 + c) * PPIX + p]) : 0.f;
        }
        __syncthreads();

        #pragma unroll
        for (int kk = 0; kk < 32; kk += 8) {
            FragA a0, a1;
            wmma::load_matrix_sync(a0, sA + wm * 40 + kk, 40);
            wmma::load_matrix_sync(a1, sA + (wm + 16) * 40 + kk, 40);
            FragBR b0, b1;
            wmma::load_matrix_sync(b0, sB + kk * 72 + wn, 72);
            wmma::load_matrix_sync(b1, sB + kk * 72 + wn + 16, 72);
            wmma::mma_sync(acc[0][0], a0, b0, acc[0][0]);
            wmma::mma_sync(acc[0][1], a0, b1, acc[0][1]);
            wmma::mma_sync(acc[1][0], a1, b0, acc[1][0]);
            wmma::mma_sync(acc[1][1], a1, b1, acc[1][1]);
        }
        __syncthreads();
    }

    #pragma unroll
    for (int i = 0; i < 2; i++)
        #pragma unroll
        for (int j = 0; j < 2; j++)
            wmma::store_matrix_sync(sC + (wm + i * 16) * 68 + wn + j * 16,
                                    acc[i][j], 68, wmma::mem_row_major);
    __syncthreads();

    const int m = tid & 127;
    const int half = tid >> 7;
    const int o = m0 + m;
    const int h = o >> 6, d = o & 63;
    const float bb = bias[o];
    float* ob = Og + (((size_t)b * HEADS + h) * PPIX) * DH + d;
    #pragma unroll
    for (int i = 0; i < 32; i++) {
        int pl = half * 32 + i;
        int p = n0 + pl;
        if (p < PPIX) ob[(size_t)p * DH] = sC[m * 68 + pl] + bb;
    }
}

// ============================================================================
// Kernel 2: attention per (b, h, qtile of 64). 512 threads, keys padded to 208.
// ============================================================================
__global__ void __launch_bounds__(512)
attn_tc()
{
    extern __shared__ float sm[];
    float* sQ   = sm;                    // 64*72 (Q, later AV partial kh=0)
    float* sC2  = sQ + 64 * 72;          // 64*72 (AV partial kh=1)
    float* sKV  = sC2 + 64 * 72;         // 208*72 (K then V)
    float* sS   = sKV + 208 * 72;        // 64*216
    float* sSum = sS + 64 * 216;         // 64

    const int tid = threadIdx.x;
    const int w   = tid >> 5;
    const int b  = blockIdx.z;
    const int h  = blockIdx.y;
    const int q0 = blockIdx.x * 64;

    const size_t bh = (size_t)b * HEADS + h;
    const float* Qg = g_q + bh * PD;
    const float* Kg = g_k + bh * PD;
    const float* Vg = g_v + bh * PD;

    // fill Q (scaled by 1/8)
    for (int idx = tid; idx < 64 * 16; idx += 512) {
        int r = idx >> 4, c4 = (idx & 15) * 4;
        int gq = q0 + r;
        float4 v = make_float4(0.f, 0.f, 0.f, 0.f);
        if (gq < PPIX) v = *(const float4*)(Qg + (size_t)gq * DH + c4);
        float* dst = sQ + r * 72 + c4;
        dst[0] = f2tf(v.x * 0.125f); dst[1] = f2tf(v.y * 0.125f);
        dst[2] = f2tf(v.z * 0.125f); dst[3] = f2tf(v.w * 0.125f);
    }
    // fill K (208 rows, zero pad)
    for (int idx = tid; idx < NPAD * 16; idx += 512) {
        int r = idx >> 4, c4 = (idx & 15) * 4;
        float4 v = make_float4(0.f, 0.f, 0.f, 0.f);
        if (r < PPIX) v = *(const float4*)(Kg + (size_t)r * DH + c4);
        float* dst = sKV + r * 72 + c4;
        dst[0] = f2tf(v.x); dst[1] = f2tf(v.y); dst[2] = f2tf(v.z); dst[3] = f2tf(v.w);
    }
    __syncthreads();

    // ---- phase A: S = Q K^T  (64 x 208) ----
    {
        const int wm = (w >> 2) * 16;
        const int g  = w & 3;
        const int cnt   = (g == 0) ? 4 : 3;
        const int jbase = (g == 0) ? 0 : (3 * g + 1);
        FragC acc[4];
        #pragma unroll
        for (int j = 0; j < 4; j++) wmma::fill_fragment(acc[j], 0.f);
        #pragma unroll
        for (int kk = 0; kk < 64; kk += 8) {
            FragA a;
            wmma::load_matrix_sync(a, sQ + wm * 72 + kk, 72);
            for (int j = 0; j < cnt; j++) {
                FragBC bf;
                wmma::load_matrix_sync(bf, sKV + (jbase + j) * 16 * 72 + kk, 72);
                wmma::mma_sync(acc[j], a, bf, acc[j]);
            }
        }
        for (int j = 0; j < cnt; j++)
            wmma::store_matrix_sync(sS + wm * 216 + (jbase + j) * 16, acc[j], 216,
                                    wmma::mem_row_major);
    }
    __syncthreads();

    // ---- softmax (8 threads per row) ----
    {
        int row = tid >> 3, j = tid & 7;
        float* srow = sS + row * 216;
        float m = -1e30f;
        for (int c = j; c < PPIX; c += 8) m = fmaxf(m, srow[c]);
        m = fmaxf(m, __shfl_xor_sync(0xffffffffu, m, 1));
        m = fmaxf(m, __shfl_xor_sync(0xffffffffu, m, 2));
        m = fmaxf(m, __shfl_xor_sync(0xffffffffu, m, 4));
        float s = 0.f;
        for (int c = j; c < NPAD; c += 8) {
            float e = (c < PPIX) ? f2tf(expf(srow[c] - m)) : 0.f;
            srow[c] = e;
            s += e;
        }
        s += __shfl_xor_sync(0xffffffffu, s, 1);
        s += __shfl_xor_sync(0xffffffffu, s, 2);
        s += __shfl_xor_sync(0xffffffffu, s, 4);
        if (j == 0) sSum[row] = s;
    }
    __syncthreads();

    // fill V (overwrite K)
    for (int idx = tid; idx < NPAD * 16; idx += 512) {
        int r = idx >> 4, c4 = (idx & 15) * 4;
        float4 v = make_float4(0.f, 0.f, 0.f, 0.f);
        if (r < PPIX) v = *(const float4*)(Vg + (size_t)r * DH + c4);
        float* dst = sKV + r * 72 + c4;
        dst[0] = f2tf(v.x); dst[1] = f2tf(v.y); dst[2] = f2tf(v.z); dst[3] = f2tf(v.w);
    }
    __syncthreads();

    // ---- phase C: AV = P V, K split in halves of 104 across warp groups ----
    {
        const int kh = w >> 3;
        const int r2 = w & 7;
        const int wm = (r2 >> 1) * 16;
        const int wn = (r2 & 1) * 32;
        FragC acc[2];
        wmma::fill_fragment(acc[0], 0.f);
        wmma::fill_fragment(acc[1], 0.f);
        #pragma unroll
        for (int s = 0; s < 13; s++) {
            int k = kh * 104 + s * 8;
            FragA a;
            wmma::load_matrix_sync(a, sS + wm * 216 + k, 216);
            FragBR b0, b1;
            wmma::load_matrix_sync(b0, sKV + k * 72 + wn, 72);
            wmma::load_matrix_sync(b1, sKV + k * 72 + wn + 16, 72);
            wmma::mma_sync(acc[0], a, b0, acc[0]);
            wmma::mma_sync(acc[1], a, b1, acc[1]);
        }
        float* buf = kh ? sC2 : sQ;
        wmma::store_matrix_sync(buf + wm * 72 + wn,      acc[0], 72, wmma::mem_row_major);
        wmma::store_matrix_sync(buf + wm * 72 + wn + 16, acc[1], 72, wmma::mem_row_major);
    }
    __syncthreads();

    // epilogue: normalize, write flat av [p][h*64+d]
    float* avb = g_av + (size_t)b * (PPIX * SDIM);
    const int d = tid & 63;
    #pragma unroll
    for (int r = 0; r < 8; r++) {
        int q = (tid >> 6) + r * 8;
        int gq = q0 + q;
        if (gq < PPIX) {
            float inv = 1.f / sSum[q];
            avb[(size_t)h * PD + (size_t)gq * DH + d] =
                (sQ[q * 72 + d] + sC2[q * 72 + d]) * inv;
        }
    }
}

// ============================================================================
// Kernel 3: output projection. CTA 128(M=o) x 64(N=p), warp 32x32.
// ============================================================================
__global__ void __launch_bounds__(256)
outproj_tc(const float* __restrict__ wo, const float* __restrict__ bo,
           float* __restrict__ out)
{
    extern __shared__ float sm[];
    float* sA  = sm;              // 128*40
    float* sBo = sm + 128 * 40;   // 64*40
    float* sC  = sm;              // reuse: 128*68

    const int tid  = threadIdx.x;
    const int w    = tid >> 5;
    const int lane = tid & 31;
    const int n0 = (blockIdx.x & 3) * 64;
    const int m0 = (blockIdx.x >> 2) * 128;
    const int b  = blockIdx.y;

    const int wm = (w >> 1) * 32;
    const int wn = (w & 1) * 32;

    FragC acc[2][2];
    #pragma unroll
    for (int i = 0; i < 2; i++)
        #pragma unroll
        for (int j = 0; j < 2; j++) wmma::fill_fragment(acc[i][j], 0.f);

    const float* avb = g_av + (size_t)b * (PPIX * SDIM);

    for (int k0 = 0; k0 < SDIM; k0 += 32) {
        #pragma unroll
        for (int r = 0; r < 16; r++) {
            int row = (tid >> 5) + r * 8;
            sA[row * 40 + lane] = f2tf(wo[(size_t)(m0 + row) * SDIM + k0 + lane]);
        }
        #pragma unroll
        for (int r = 0; r < 8; r++) {
            int prow = (tid >> 5) + r * 8;
            int p = n0 + prow;
            sBo[prow * 40 + lane] =
                (p < PPIX) ? f2tf(avb[(size_t)p * SDIM + k0 + lane]) : 0.f;
        }
        __syncthreads();

        #pragma unroll
        for (int kk = 0; kk < 32; kk += 8) {
            FragA a0, a1;
            wmma::load_matrix_sync(a0, sA + wm * 40 + kk, 40);
            wmma::load_matrix_sync(a1, sA + (wm + 16) * 40 + kk, 40);
            FragBC b0, b1;
            wmma::load_matrix_sync(b0, sBo + wn * 40 + kk, 40);
            wmma::load_matrix_sync(b1, sBo + (wn + 16) * 40 + kk, 40);
            wmma::mma_sync(acc[0][0], a0, b0, acc[0][0]);
            wmma::mma_sync(acc[0][1], a0, b1, acc[0][1]);
            wmma::mma_sync(acc[1][0], a1, b0, acc[1][0]);
            wmma::mma_sync(acc[1][1], a1, b1, acc[1][1]);
        }
        __syncthreads();
    }

    #pragma unroll
    for (int i = 0; i < 2; i++)
        #pragma unroll
        for (int j = 0; j < 2; j++)
            wmma::store_matrix_sync(sC + (wm + i * 16) * 68 + wn + j * 16,
                                    acc[i][j], 68, wmma::mem_row_major);
    __syncthreads();

    const int m = tid >> 1;
    const int half = tid & 1;
    const int o = m0 + m;
    const float bb = bo[o];
    float* orow = out + ((size_t)b * SDIM + o) * PPIX;
    if (n0 + 63 < PPIX) {
        #pragma unroll
        for (int i = 0; i < 8; i++) {
            int pl = half * 32 + i * 4;
            float4 v;
            v.x = sC[m * 68 + pl + 0] + bb;
            v.y = sC[m * 68 + pl + 1] + bb;
            v.z = sC[m * 68 + pl + 2] + bb;
            v.w = sC[m * 68 + pl + 3] + bb;
            *(float4*)(orow + n0 + pl) = v;
        }
    } else {
        #pragma unroll
        for (int i = 0; i < 32; i++) {
            int pl = half * 32 + i;
            int p = n0 + pl;
            if (p < PPIX) orow[p] = sC[m * 68 + pl] + bb;
        }
    }
}

// ============================================================================
extern "C" void kernel_launch(void* const* d_in, const int* in_sizes, int n_in,
                              void* d_out, int out_size)
{
    const float* x  = (const float*)d_in[0];
    const float* wq = (const float*)d_in[1];
    const float* bq = (const float*)d_in[2];
    const float* wk = (const float*)d_in[3];
    const float* bk = (const float*)d_in[4];
    const float* wv = (const float*)d_in[5];
    const float* bv = (const float*)d_in[6];
    const float* wo = (const float*)d_in[7];
    const float* bo = (const float*)d_in[8];
    float* out = (float*)d_out;

    const int gemm_smem = 128 * 68 * 4;   // 34,816 B (union of tiles / epilogue)

    qkv_tc<<<dim3(8, 3, BATCH), 256, gemm_smem>>>(x, wq, bq, wk, bk, wv, bv);

    const int attn_smem = (64 * 72 * 2 + NPAD * 72 + 64 * 216 + 64) * sizeof(float); // 152,320
    cudaFuncSetAttribute(attn_tc, cudaFuncAttributeMaxDynamicSharedMemorySize, attn_smem);
    attn_tc<<<dim3(4, HEADS, BATCH), 512, attn_smem>>>();

    outproj_tc<<<dim3(8, BATCH), 256, gemm_smem>>>(wo, bo, out);
}